// round 4
// baseline (speedup 1.0000x reference)
#include <cuda_runtime.h>
#include <cuda_fp16.h>

#define Bc  4
#define Tc  2048
#define Dc  1024
#define Hc  16
#define HDc 64
#define NTOK (Bc * Tc)   // 8192

// Scratch: __device__ globals (no allocation allowed in kernel_launch).
// Q/K/V stored head-permuted: [B,H,T,HD]  (32 MB each)
__device__ float  g_Q[(size_t)NTOK * Dc];
__device__ float  g_K[(size_t)NTOK * Dc];
__device__ float  g_V[(size_t)NTOK * Dc];
// Raw scores (pre-softmax, scaled) fp16: [B*H, T(q), T(k)]  (512 MB)
__device__ __half g_S[(size_t)Bc * Hc * Tc * Tc];
// Per-row softmax offset c[q] = m[q] + log(Z[q])  so p = exp(s - c)
__device__ float  g_c[Bc * Hc * Tc];
// Column weights w[k] = (1/T) * sum_q p[q,k]
__device__ float  g_w[Bc * Hc * Tc];
// Mean attention output before Wo: [B, D]
__device__ float  g_ctx[Bc * Dc];

// ---------------------------------------------------------------------------
// Kernel 1: QKV projection.  out[n, j] = sum_d x[n,d] * W[j,d] + bias[j]
// Tile 64(tokens) x 64(one head), BK=16, 256 threads, 4x4 microtile.
// Output scattered to [B,H,T,HD] layout (tile column block == one head).
// ---------------------------------------------------------------------------
__global__ __launch_bounds__(256) void qkv_kernel(
    const float* __restrict__ x, const float* __restrict__ W,
    const float* __restrict__ bias, int sel)
{
    __shared__ float As[16][68];   // [k][token], pad 4 keeps 16B alignment
    __shared__ float Bs[16][68];   // [k][j]
    float* out = (sel == 0) ? g_Q : (sel == 1) ? g_K : g_V;

    const int tid  = threadIdx.x;
    const int tx   = tid & 15, ty = tid >> 4;
    const int n0   = blockIdx.x * 64;
    const int h    = blockIdx.y;
    const int j0   = h * 64;
    const int lrow = tid >> 2;
    const int lk   = (tid & 3) * 4;

    float acc[4][4];
#pragma unroll
    for (int i = 0; i < 4; i++)
#pragma unroll
        for (int j = 0; j < 4; j++) acc[i][j] = 0.f;

    const float* xr = x + (size_t)(n0 + lrow) * Dc;
    const float* wr = W + (size_t)(j0 + lrow) * Dc;

    for (int k0 = 0; k0 < Dc; k0 += 16) {
        float4 av = *(const float4*)(xr + k0 + lk);
        float4 bv = *(const float4*)(wr + k0 + lk);
        As[lk+0][lrow] = av.x; As[lk+1][lrow] = av.y;
        As[lk+2][lrow] = av.z; As[lk+3][lrow] = av.w;
        Bs[lk+0][lrow] = bv.x; Bs[lk+1][lrow] = bv.y;
        Bs[lk+2][lrow] = bv.z; Bs[lk+3][lrow] = bv.w;
        __syncthreads();
#pragma unroll
        for (int kk = 0; kk < 16; kk++) {
            float4 a = *(const float4*)&As[kk][ty * 4];
            float4 b = *(const float4*)&Bs[kk][tx * 4];
            acc[0][0] += a.x*b.x; acc[0][1] += a.x*b.y; acc[0][2] += a.x*b.z; acc[0][3] += a.x*b.w;
            acc[1][0] += a.y*b.x; acc[1][1] += a.y*b.y; acc[1][2] += a.y*b.z; acc[1][3] += a.y*b.w;
            acc[2][0] += a.z*b.x; acc[2][1] += a.z*b.y; acc[2][2] += a.z*b.z; acc[2][3] += a.z*b.w;
            acc[3][0] += a.w*b.x; acc[3][1] += a.w*b.y; acc[3][2] += a.w*b.z; acc[3][3] += a.w*b.w;
        }
        __syncthreads();
    }

    const int b = n0 >> 11;   // T = 2048 tokens per batch
    float4 bb = *(const float4*)(bias + j0 + tx * 4);
#pragma unroll
    for (int i = 0; i < 4; i++) {
        int t = (n0 + ty * 4 + i) & (Tc - 1);
        float4 o;
        o.x = acc[i][0] + bb.x; o.y = acc[i][1] + bb.y;
        o.z = acc[i][2] + bb.z; o.w = acc[i][3] + bb.w;
        *(float4*)(out + ((size_t)((b * Hc + h) * Tc + t)) * HDc + tx * 4) = o;
    }
}

// ---------------------------------------------------------------------------
// Kernel 2: scores S = (Q * scale) . K^T per (b,h); store fp16; track
// per-row running max m and sum Z online; emit c[q] = m + log(Z).
// Block: 64 queries, loops over all 2048 keys in tiles of 64.
// ---------------------------------------------------------------------------
__global__ __launch_bounds__(256) void score_kernel()
{
    __shared__ float Qs[64][68];   // [d][q]
    __shared__ float Ks[64][68];   // [d][k]
    const int tid = threadIdx.x;
    const int tx  = tid & 15, ty = tid >> 4;
    const int bh  = blockIdx.y;
    const int q0  = blockIdx.x * 64;
    const int lrow = tid >> 2;
    const int lc   = tid & 3;

    const float* Qb = g_Q + ((size_t)bh * Tc + q0) * HDc;
    const float* Kb = g_K + (size_t)bh * Tc * HDc;
    __half*      Sb = g_S + (size_t)bh * Tc * Tc;

#pragma unroll
    for (int it = 0; it < 4; it++) {
        int d0 = (lc + it * 4) * 4;
        float4 v = *(const float4*)(Qb + (size_t)lrow * HDc + d0);
        Qs[d0+0][lrow] = v.x * 0.125f; Qs[d0+1][lrow] = v.y * 0.125f;
        Qs[d0+2][lrow] = v.z * 0.125f; Qs[d0+3][lrow] = v.w * 0.125f;
    }

    float rowm[4], rowz[4];
#pragma unroll
    for (int i = 0; i < 4; i++) { rowm[i] = -1e30f; rowz[i] = 0.f; }

    for (int k0 = 0; k0 < Tc; k0 += 64) {
        __syncthreads();   // prior-iter reads done before Ks overwrite
#pragma unroll
        for (int it = 0; it < 4; it++) {
            int d0 = (lc + it * 4) * 4;
            float4 v = *(const float4*)(Kb + (size_t)(k0 + lrow) * HDc + d0);
            Ks[d0+0][lrow] = v.x; Ks[d0+1][lrow] = v.y;
            Ks[d0+2][lrow] = v.z; Ks[d0+3][lrow] = v.w;
        }
        __syncthreads();

        float acc[4][4];
#pragma unroll
        for (int i = 0; i < 4; i++)
#pragma unroll
            for (int j = 0; j < 4; j++) acc[i][j] = 0.f;

#pragma unroll 16
        for (int d = 0; d < 64; d++) {
            float4 a = *(const float4*)&Qs[d][ty * 4];
            float4 b = *(const float4*)&Ks[d][tx * 4];
            acc[0][0] += a.x*b.x; acc[0][1] += a.x*b.y; acc[0][2] += a.x*b.z; acc[0][3] += a.x*b.w;
            acc[1][0] += a.y*b.x; acc[1][1] += a.y*b.y; acc[1][2] += a.y*b.z; acc[1][3] += a.y*b.w;
            acc[2][0] += a.z*b.x; acc[2][1] += a.z*b.y; acc[2][2] += a.z*b.z; acc[2][3] += a.z*b.w;
            acc[3][0] += a.w*b.x; acc[3][1] += a.w*b.y; acc[3][2] += a.w*b.z; acc[3][3] += a.w*b.w;
        }

#pragma unroll
        for (int i = 0; i < 4; i++) {
            float s0 = acc[i][0], s1 = acc[i][1], s2 = acc[i][2], s3 = acc[i][3];
            size_t sidx = (size_t)(q0 + ty * 4 + i) * Tc + k0 + tx * 4;
            *(__half2*)(Sb + sidx)     = __floats2half2_rn(s0, s1);
            *(__half2*)(Sb + sidx + 2) = __floats2half2_rn(s2, s3);
            float mx = fmaxf(fmaxf(s0, s1), fmaxf(s2, s3));
            float nm = fmaxf(rowm[i], mx);
            float za = __expf(s0 - nm) + __expf(s1 - nm)
                     + __expf(s2 - nm) + __expf(s3 - nm);
            rowz[i] = rowz[i] * __expf(rowm[i] - nm) + za;
            rowm[i] = nm;
        }
    }

    // Reduce 16 (m,z) partials per query row (threads sharing ty).
    __syncthreads();
    float* redm = &Qs[0][0];
    float* redz = &Ks[0][0];
#pragma unroll
    for (int i = 0; i < 4; i++) {
        redm[(ty * 4 + i) * 16 + tx] = rowm[i];
        redz[(ty * 4 + i) * 16 + tx] = rowz[i];
    }
    __syncthreads();
    if (tid < 64) {
        float M = -1e30f, Z = 0.f;
#pragma unroll
        for (int j = 0; j < 16; j++) {
            float mj = redm[tid * 16 + j], zj = redz[tid * 16 + j];
            float nm = fmaxf(M, mj);
            Z = Z * __expf(M - nm) + zj * __expf(mj - nm);
            M = nm;
        }
        g_c[bh * Tc + q0 + tid] = M + __logf(Z);
    }
}

// ---------------------------------------------------------------------------
// Kernel 3: column sums  w[k] = (1/T) * sum_q exp(S[q,k] - c[q]).
// Memory-bound pass over 512 MB of fp16 scores.
// ---------------------------------------------------------------------------
__global__ __launch_bounds__(256) void colsum_kernel()
{
    const int bh = blockIdx.y;
    const int k  = blockIdx.x * 256 + threadIdx.x;
    const __half* Sb = g_S + (size_t)bh * Tc * Tc;
    const float*  cb = g_c + bh * Tc;
    float a0 = 0.f, a1 = 0.f, a2 = 0.f, a3 = 0.f;
    for (int q = 0; q < Tc; q += 4) {
        a0 += __expf(__half2float(Sb[(size_t)(q + 0) * Tc + k]) - cb[q + 0]);
        a1 += __expf(__half2float(Sb[(size_t)(q + 1) * Tc + k]) - cb[q + 1]);
        a2 += __expf(__half2float(Sb[(size_t)(q + 2) * Tc + k]) - cb[q + 2]);
        a3 += __expf(__half2float(Sb[(size_t)(q + 3) * Tc + k]) - cb[q + 3]);
    }
    g_w[bh * Tc + k] = (a0 + a1 + a2 + a3) * (1.0f / Tc);
}

// ---------------------------------------------------------------------------
// Kernel 4: ctx[b, h*64+d] = sum_k w[b,h,k] * V[b,h,k,d]   (w has 1/T folded)
// ---------------------------------------------------------------------------
__global__ __launch_bounds__(256) void ctx_kernel()
{
    const int bh   = blockIdx.x;
    const int d    = threadIdx.x & 63;
    const int part = threadIdx.x >> 6;       // 4-way k split
    const float* Vb = g_V + (size_t)bh * Tc * HDc;
    const float* wb = g_w + bh * Tc;
    float acc = 0.f;
    const int kb = part * (Tc / 4);
    for (int k = kb; k < kb + Tc / 4; k++)
        acc += wb[k] * Vb[(size_t)k * HDc + d];
    __shared__ float red[4][64];
    red[part][d] = acc;
    __syncthreads();
    if (part == 0) {
        int b = bh >> 4, h = bh & 15;
        g_ctx[b * Dc + h * HDc + d] =
            red[0][d] + red[1][d] + red[2][d] + red[3][d];
    }
}

// ---------------------------------------------------------------------------
// Kernel 5: out[b, j] = sum_i ctx[b,i] * Wo[j,i] + bo[j]
// ---------------------------------------------------------------------------
__global__ __launch_bounds__(128) void out_kernel(
    const float* __restrict__ Wo, const float* __restrict__ bo,
    float* __restrict__ out)
{
    __shared__ float cs[Bc * Dc];
    const int tid = threadIdx.x;
    for (int i = tid; i < Bc * Dc; i += 128) cs[i] = g_ctx[i];
    __syncthreads();
    const int j = blockIdx.x * 128 + tid;
    const float* wr = Wo + (size_t)j * Dc;
    float a0 = 0.f, a1 = 0.f, a2 = 0.f, a3 = 0.f;
    for (int i = 0; i < Dc; i += 4) {
        float4 wv = *(const float4*)(wr + i);
        a0 += cs[i]*wv.x        + cs[i+1]*wv.y        + cs[i+2]*wv.z        + cs[i+3]*wv.w;
        a1 += cs[Dc+i]*wv.x     + cs[Dc+i+1]*wv.y     + cs[Dc+i+2]*wv.z     + cs[Dc+i+3]*wv.w;
        a2 += cs[2*Dc+i]*wv.x   + cs[2*Dc+i+1]*wv.y   + cs[2*Dc+i+2]*wv.z   + cs[2*Dc+i+3]*wv.w;
        a3 += cs[3*Dc+i]*wv.x   + cs[3*Dc+i+1]*wv.y   + cs[3*Dc+i+2]*wv.z   + cs[3*Dc+i+3]*wv.w;
    }
    float bj = bo[j];
    out[0*Dc + j] = a0 + bj;
    out[1*Dc + j] = a1 + bj;
    out[2*Dc + j] = a2 + bj;
    out[3*Dc + j] = a3 + bj;
}

// ---------------------------------------------------------------------------
extern "C" void kernel_launch(void* const* d_in, const int* in_sizes, int n_in,
                              void* d_out, int out_size)
{
    const float* x  = (const float*)d_in[0];
    const float* Wq = (const float*)d_in[1];
    const float* bq = (const float*)d_in[2];
    const float* Wk = (const float*)d_in[3];
    const float* bk = (const float*)d_in[4];
    const float* Wv = (const float*)d_in[5];
    const float* bv = (const float*)d_in[6];
    const float* Wo = (const float*)d_in[7];
    const float* bo = (const float*)d_in[8];

    dim3 gq(NTOK / 64, Hc);
    qkv_kernel<<<gq, 256>>>(x, Wq, bq, 0);
    qkv_kernel<<<gq, 256>>>(x, Wk, bk, 1);
    qkv_kernel<<<gq, 256>>>(x, Wv, bv, 2);
    score_kernel<<<dim3(Tc / 64, Bc * Hc), 256>>>();
    colsum_kernel<<<dim3(Tc / 256, Bc * Hc), 256>>>();
    ctx_kernel<<<Bc * Hc, 256>>>();
    out_kernel<<<Dc / 128, 128>>>(Wo, bo, (float*)d_out);
}

// round 5
// speedup vs baseline: 2.8267x; 2.8267x over previous
#include <cuda_runtime.h>
#include <cuda_fp16.h>
#include <cstdint>

#define Bc  4
#define Tc  2048
#define Dc  1024
#define Hc  16
#define HDc 64
#define NTOK (Bc * Tc)   // 8192

// ---------------- scratch (__device__ globals; no allocs allowed) ----------
__device__ __half g_xh[(size_t)NTOK * Dc];          // x in fp16
__device__ __half g_Wh[(size_t)3 * Dc * Dc];        // Wq,Wk,Wv in fp16
__device__ __half g_Qh[(size_t)NTOK * Dc];          // [B,H,T,HD] fp16 (pre-scaled by 0.125)
__device__ __half g_Kh[(size_t)NTOK * Dc];          // [B,H,T,HD] fp16
__device__ float  g_V [(size_t)NTOK * Dc];          // [B,H,T,HD] fp32
__device__ __half g_S [(size_t)Bc * Hc * Tc * Tc];  // raw scores fp16 (512 MB)
__device__ float  g_c [Bc * Hc * Tc];               // per-row m + log Z
__device__ float  g_w [Bc * Hc * Tc];               // column weights (1/T folded)
__device__ float  g_ctx[Bc * Dc];                   // mean attn output

// ---------------- PTX helpers ---------------------------------------------
__device__ __forceinline__ uint32_t smem_u32(const void* p) {
    return (uint32_t)__cvta_generic_to_shared(p);
}
__device__ __forceinline__ void cp16(uint32_t dst, const void* src) {
    asm volatile("cp.async.cg.shared.global [%0], [%1], 16;\n" :: "r"(dst), "l"(src));
}
__device__ __forceinline__ void cp_commit() { asm volatile("cp.async.commit_group;\n"); }
template<int N> __device__ __forceinline__ void cp_wait() {
    asm volatile("cp.async.wait_group %0;\n" :: "n"(N));
}
__device__ __forceinline__ void ldsm4(uint32_t* r, uint32_t a) {
    asm volatile("ldmatrix.sync.aligned.m8n8.x4.shared.b16 {%0,%1,%2,%3},[%4];\n"
        : "=r"(r[0]), "=r"(r[1]), "=r"(r[2]), "=r"(r[3]) : "r"(a));
}
__device__ __forceinline__ void ldsm2(uint32_t* r, uint32_t a) {
    asm volatile("ldmatrix.sync.aligned.m8n8.x2.shared.b16 {%0,%1},[%2];\n"
        : "=r"(r[0]), "=r"(r[1]) : "r"(a));
}
__device__ __forceinline__ void mma16816(float* d, const uint32_t* a, const uint32_t* b) {
    asm volatile("mma.sync.aligned.m16n8k16.row.col.f32.f16.f16.f32 "
        "{%0,%1,%2,%3},{%4,%5,%6,%7},{%8,%9},{%0,%1,%2,%3};\n"
        : "+f"(d[0]), "+f"(d[1]), "+f"(d[2]), "+f"(d[3])
        : "r"(a[0]), "r"(a[1]), "r"(a[2]), "r"(a[3]), "r"(b[0]), "r"(b[1]));
}

// ---------------------------------------------------------------------------
// Kernel 0: fp32 -> fp16 conversion of x and the three projection weights.
// ---------------------------------------------------------------------------
__global__ __launch_bounds__(256) void convert_kernel(
    const float* __restrict__ x, const float* __restrict__ Wq,
    const float* __restrict__ Wk, const float* __restrict__ Wv)
{
    const size_t NX = (size_t)NTOK * Dc;       // 8388608
    const size_t NW = (size_t)Dc * Dc;         // 1048576
    size_t i = ((size_t)blockIdx.x * 256 + threadIdx.x) * 4;
    if (i < NX) {
        float4 v = *(const float4*)(x + i);
        *(__half2*)(g_xh + i)     = __floats2half2_rn(v.x, v.y);
        *(__half2*)(g_xh + i + 2) = __floats2half2_rn(v.z, v.w);
    } else {
        size_t j = i - NX;
        if (j >= 3 * NW) return;
        const float* src = (j < NW) ? (Wq + j) : (j < 2 * NW) ? (Wk + (j - NW)) : (Wv + (j - 2 * NW));
        float4 v = *(const float4*)src;
        __half* dst = g_Wh + j;
        *(__half2*)dst       = __floats2half2_rn(v.x, v.y);
        *(__half2*)(dst + 2) = __floats2half2_rn(v.z, v.w);
    }
}

// ---------------------------------------------------------------------------
// Kernel 1: QKV projection via fp16 mma.  out[n,j] = sum_d xh[n,d]*Wh[j,d]+b.
// Tile 128(tokens) x 64(one head), BK=32, 8 warps (2x4), double-buffered
// cp.async.  grid = (64, 16 heads, 3 sel).  Q is stored *0.125 (softmax
// scale folded).  Q,K -> fp16 [B,H,T,HD]; V -> fp32.
// ---------------------------------------------------------------------------
#define QK_BM 128
#define QK_BN 64
#define QK_BK 32
#define QK_ST 40   // 32 + 8 pad halves (80B stride: ldmatrix conflict-free)

__global__ __launch_bounds__(256) void qkv_mma_kernel(
    const float* __restrict__ bq, const float* __restrict__ bk,
    const float* __restrict__ bv)
{
    __shared__ __half As[2][QK_BM][QK_ST];
    __shared__ __half Bs[2][QK_BN][QK_ST];

    const int tid  = threadIdx.x;
    const int lane = tid & 31, warp = tid >> 5;
    const int wm = warp >> 2, wn = warp & 3;     // 2 x 4 warp grid
    const int sel = blockIdx.z;
    const int h   = blockIdx.y;
    const int n0  = blockIdx.x * QK_BM;
    const int j0  = h * 64;
    const __half* WB   = g_Wh + (size_t)sel * Dc * Dc;
    const float*  bias = (sel == 0) ? bq : (sel == 1) ? bk : bv;

    const int arow = tid >> 1, ac0 = (tid & 1) * 2;  // A: 2 chunks/thread
    const int brow = tid >> 2, bc  = tid & 3;        // B: 1 chunk/thread

    float acc[4][2][4];
#pragma unroll
    for (int mt = 0; mt < 4; mt++)
#pragma unroll
        for (int nt = 0; nt < 2; nt++)
#pragma unroll
            for (int i = 0; i < 4; i++) acc[mt][nt][i] = 0.f;

    // stage-0 preload
    {
        const __half* sa = g_xh + (size_t)(n0 + arow) * Dc + ac0 * 8;
        uint32_t da = smem_u32(&As[0][arow][ac0 * 8]);
        cp16(da, sa); cp16(da + 16, sa + 8);
        cp16(smem_u32(&Bs[0][brow][bc * 8]), WB + (size_t)(j0 + brow) * Dc + bc * 8);
        cp_commit();
    }

    const int NKT = Dc / QK_BK;   // 32
    for (int kt = 0; kt < NKT; kt++) {
        if (kt + 1 < NKT) {
            int s = (kt + 1) & 1, k0 = (kt + 1) * QK_BK;
            const __half* sa = g_xh + (size_t)(n0 + arow) * Dc + k0 + ac0 * 8;
            uint32_t da = smem_u32(&As[s][arow][ac0 * 8]);
            cp16(da, sa); cp16(da + 16, sa + 8);
            cp16(smem_u32(&Bs[s][brow][bc * 8]), WB + (size_t)(j0 + brow) * Dc + k0 + bc * 8);
            cp_commit();
            cp_wait<1>();
        } else {
            cp_wait<0>();
        }
        __syncthreads();
        const int s = kt & 1;
#pragma unroll
        for (int ks = 0; ks < 2; ks++) {
            uint32_t af[4][4], bf[2][2];
#pragma unroll
            for (int mt = 0; mt < 4; mt++)
                ldsm4(af[mt], smem_u32(&As[s][wm * 64 + mt * 16 + (lane & 15)][ks * 16 + (lane >> 4) * 8]));
#pragma unroll
            for (int nt = 0; nt < 2; nt++)
                ldsm2(bf[nt], smem_u32(&Bs[s][wn * 16 + nt * 8 + (lane & 7)][ks * 16 + ((lane >> 3) & 1) * 8]));
#pragma unroll
            for (int mt = 0; mt < 4; mt++)
#pragma unroll
                for (int nt = 0; nt < 2; nt++)
                    mma16816(acc[mt][nt], af[mt], bf[nt]);
        }
        __syncthreads();
    }

    // epilogue: bias + scatter to [B,H,T,HD]
    const int gr = lane >> 2, gc = lane & 3;
    const int b  = n0 >> 11;
#pragma unroll
    for (int mt = 0; mt < 4; mt++) {
#pragma unroll
        for (int nt = 0; nt < 2; nt++) {
            const int cw = wn * 16 + nt * 8 + gc * 2;   // col within head
            const float b0 = bias[j0 + cw], b1 = bias[j0 + cw + 1];
#pragma unroll
            for (int hf = 0; hf < 2; hf++) {
                const int r = wm * 64 + mt * 16 + gr + hf * 8;
                const int t = (n0 + r) & (Tc - 1);
                const size_t off = ((size_t)((b * Hc + h) * Tc + t)) * HDc + cw;
                float v0 = acc[mt][nt][hf * 2 + 0] + b0;
                float v1 = acc[mt][nt][hf * 2 + 1] + b1;
                if (sel == 0)      *(__half2*)(g_Qh + off) = __floats2half2_rn(v0 * 0.125f, v1 * 0.125f);
                else if (sel == 1) *(__half2*)(g_Kh + off) = __floats2half2_rn(v0, v1);
                else               *(float2*)(g_V + off)   = make_float2(v0, v1);
            }
        }
    }
}

// ---------------------------------------------------------------------------
// Kernel 2: scores via fp16 mma, fused online logsumexp + fp16 store.
// Block: 128 queries x all keys (tiles of 64).  Q fragments preloaded once.
// 8 warps: wm 0..3 (32 rows), wn 0..1 (32 cols of the 64-key tile).
// ---------------------------------------------------------------------------
#define SC_BM 128
#define SC_BN 64
#define SC_ST (HDc + 8)   // 72 halves (144B stride: conflict-free)

__global__ __launch_bounds__(256) void score_mma_kernel()
{
    __shared__ __half Qs[SC_BM][SC_ST];
    __shared__ __half Ks[2][SC_BN][SC_ST];
    __shared__ float  redm[SC_BM][2], redz[SC_BM][2];

    const int tid = threadIdx.x, lane = tid & 31, warp = tid >> 5;
    const int wm = warp >> 1, wn = warp & 1;
    const int bh = blockIdx.y, q0 = blockIdx.x * SC_BM;
    const __half* Qg = g_Qh + ((size_t)bh * Tc + q0) * HDc;
    const __half* Kg = g_Kh + (size_t)bh * Tc * HDc;
    __half*       Sb = g_S  + (size_t)bh * Tc * Tc;

    // load Q tile (128 x 64 halves) — 4 chunks/thread
    {
        int id = tid;
#pragma unroll
        for (int it = 0; it < 4; it++, id += 256) {
            int r = id >> 3, c = id & 7;
            cp16(smem_u32(&Qs[r][c * 8]), Qg + (size_t)r * HDc + c * 8);
        }
        cp_commit();
    }
    // K tile 0 — 2 chunks/thread
    {
        int id = tid;
#pragma unroll
        for (int it = 0; it < 2; it++, id += 256) {
            int r = id >> 3, c = id & 7;
            cp16(smem_u32(&Ks[0][r][c * 8]), Kg + (size_t)r * HDc + c * 8);
        }
        cp_commit();
    }
    cp_wait<1>();           // Q ready
    __syncthreads();

    // preload Q fragments once (reused for every key tile)
    uint32_t qf[2][4][4];
#pragma unroll
    for (int mt = 0; mt < 2; mt++)
#pragma unroll
        for (int ks = 0; ks < 4; ks++)
            ldsm4(qf[mt][ks], smem_u32(&Qs[wm * 32 + mt * 16 + (lane & 15)][ks * 16 + (lane >> 4) * 8]));

    float m_run[4], z_run[4];
#pragma unroll
    for (int i = 0; i < 4; i++) { m_run[i] = -1e30f; z_run[i] = 0.f; }

    const int gr = lane >> 2, gc = lane & 3;
    const int NKT = Tc / SC_BN;   // 32

    for (int kt = 0; kt < NKT; kt++) {
        cp_wait<0>();
        __syncthreads();
        const int s = kt & 1;

        float acc[2][4][4];
#pragma unroll
        for (int mt = 0; mt < 2; mt++)
#pragma unroll
            for (int nt = 0; nt < 4; nt++)
#pragma unroll
                for (int i = 0; i < 4; i++) acc[mt][nt][i] = 0.f;

#pragma unroll
        for (int ks = 0; ks < 4; ks++) {
            uint32_t bf[4][2];
#pragma unroll
            for (int nt = 0; nt < 4; nt++)
                ldsm2(bf[nt], smem_u32(&Ks[s][wn * 32 + nt * 8 + (lane & 7)][ks * 16 + ((lane >> 3) & 1) * 8]));
#pragma unroll
            for (int mt = 0; mt < 2; mt++)
#pragma unroll
                for (int nt = 0; nt < 4; nt++)
                    mma16816(acc[mt][nt], qf[mt][ks], bf[nt]);
        }
        __syncthreads();   // everyone done reading Ks[s] before it is refilled

        // prefetch next K tile (overlaps with epilogue below)
        if (kt + 1 < NKT) {
            int id = tid, k0 = (kt + 1) * SC_BN, sn = (kt + 1) & 1;
#pragma unroll
            for (int it = 0; it < 2; it++, id += 256) {
                int r = id >> 3, c = id & 7;
                cp16(smem_u32(&Ks[sn][r][c * 8]), Kg + (size_t)(k0 + r) * HDc + c * 8);
            }
            cp_commit();
        }

        // epilogue: fp16 store + online (m, z) update
#pragma unroll
        for (int mt = 0; mt < 2; mt++) {
#pragma unroll
            for (int hf = 0; hf < 2; hf++) {
                const int li = mt * 2 + hf;
                float v[8];
#pragma unroll
                for (int nt = 0; nt < 4; nt++) {
                    v[nt * 2]     = acc[mt][nt][hf * 2 + 0];
                    v[nt * 2 + 1] = acc[mt][nt][hf * 2 + 1];
                }
                float mx = v[0];
#pragma unroll
                for (int i = 1; i < 8; i++) mx = fmaxf(mx, v[i]);
                float nm = fmaxf(m_run[li], mx);
                float za = 0.f;
#pragma unroll
                for (int i = 0; i < 8; i++) za += __expf(v[i] - nm);
                z_run[li] = z_run[li] * __expf(m_run[li] - nm) + za;
                m_run[li] = nm;

                const int r = wm * 32 + mt * 16 + gr + hf * 8;
                size_t base = (size_t)(q0 + r) * Tc + kt * SC_BN + wn * 32 + gc * 2;
#pragma unroll
                for (int nt = 0; nt < 4; nt++)
                    *(__half2*)(Sb + base + nt * 8) = __floats2half2_rn(v[nt * 2], v[nt * 2 + 1]);
            }
        }
    }

    // reduce (m,z): quad (gc) via shfl, then the 2 n-warps via smem
#pragma unroll
    for (int li = 0; li < 4; li++) {
#pragma unroll
        for (int d = 1; d < 4; d <<= 1) {
            float om = __shfl_xor_sync(0xffffffffu, m_run[li], d);
            float oz = __shfl_xor_sync(0xffffffffu, z_run[li], d);
            float nm = fmaxf(m_run[li], om);
            z_run[li] = z_run[li] * __expf(m_run[li] - nm) + oz * __expf(om - nm);
            m_run[li] = nm;
        }
    }
    __syncthreads();
    if (gc == 0) {
#pragma unroll
        for (int li = 0; li < 4; li++) {
            const int r = wm * 32 + (li >> 1) * 16 + gr + (li & 1) * 8;
            redm[r][wn] = m_run[li];
            redz[r][wn] = z_run[li];
        }
    }
    __syncthreads();
    if (tid < SC_BM) {
        float m0 = redm[tid][0], m1 = redm[tid][1];
        float z0 = redz[tid][0], z1 = redz[tid][1];
        float nm = fmaxf(m0, m1);
        float Z  = z0 * __expf(m0 - nm) + z1 * __expf(m1 - nm);
        g_c[bh * Tc + q0 + tid] = nm + __logf(Z);
    }
}

// ---------------------------------------------------------------------------
// Kernel 3: column sums w[k] = (1/T) sum_q exp(S[q,k] - c[q]).  half2 loads.
// ---------------------------------------------------------------------------
__global__ __launch_bounds__(256) void colsum_kernel()
{
    const int bh = blockIdx.y;
    const int k2 = blockIdx.x * 256 + threadIdx.x;   // half2 column index
    const __half2* Sb = (const __half2*)(g_S + (size_t)bh * Tc * Tc) + k2;
    const float*   cb = g_c + bh * Tc;
    float a0 = 0.f, a1 = 0.f;
#pragma unroll 4
    for (int q = 0; q < Tc; q++) {
        float2 v = __half22float2(Sb[(size_t)q * (Tc / 2)]);
        float  c = cb[q];
        a0 += __expf(v.x - c);
        a1 += __expf(v.y - c);
    }
    g_w[bh * Tc + 2 * k2]     = a0 * (1.0f / Tc);
    g_w[bh * Tc + 2 * k2 + 1] = a1 * (1.0f / Tc);
}

// ---------------------------------------------------------------------------
// Kernel 4: ctx[b, h*64+d] = sum_k w[b,h,k] * V[b,h,k,d]
// ---------------------------------------------------------------------------
__global__ __launch_bounds__(256) void ctx_kernel()
{
    const int bh   = blockIdx.x;
    const int d    = threadIdx.x & 63;
    const int part = threadIdx.x >> 6;
    const float* Vb = g_V + (size_t)bh * Tc * HDc;
    const float* wb = g_w + bh * Tc;
    float acc = 0.f;
    const int kb = part * (Tc / 4);
    for (int k = kb; k < kb + Tc / 4; k++)
        acc += wb[k] * Vb[(size_t)k * HDc + d];
    __shared__ float red[4][64];
    red[part][d] = acc;
    __syncthreads();
    if (part == 0) {
        int b = bh >> 4, h = bh & 15;
        g_ctx[b * Dc + h * HDc + d] = red[0][d] + red[1][d] + red[2][d] + red[3][d];
    }
}

// ---------------------------------------------------------------------------
// Kernel 5: out[b, j] = sum_i ctx[b,i] * Wo[j,i] + bo[j]
// ---------------------------------------------------------------------------
__global__ __launch_bounds__(128) void out_kernel(
    const float* __restrict__ Wo, const float* __restrict__ bo,
    float* __restrict__ out)
{
    __shared__ float cs[Bc * Dc];
    const int tid = threadIdx.x;
    for (int i = tid; i < Bc * Dc; i += 128) cs[i] = g_ctx[i];
    __syncthreads();
    const int j = blockIdx.x * 128 + tid;
    const float* wr = Wo + (size_t)j * Dc;
    float a0 = 0.f, a1 = 0.f, a2 = 0.f, a3 = 0.f;
    for (int i = 0; i < Dc; i += 4) {
        float4 wv = *(const float4*)(wr + i);
        a0 += cs[i]*wv.x      + cs[i+1]*wv.y      + cs[i+2]*wv.z      + cs[i+3]*wv.w;
        a1 += cs[Dc+i]*wv.x   + cs[Dc+i+1]*wv.y   + cs[Dc+i+2]*wv.z   + cs[Dc+i+3]*wv.w;
        a2 += cs[2*Dc+i]*wv.x + cs[2*Dc+i+1]*wv.y + cs[2*Dc+i+2]*wv.z + cs[2*Dc+i+3]*wv.w;
        a3 += cs[3*Dc+i]*wv.x + cs[3*Dc+i+1]*wv.y + cs[3*Dc+i+2]*wv.z + cs[3*Dc+i+3]*wv.w;
    }
    float bj = bo[j];
    out[0*Dc + j] = a0 + bj;
    out[1*Dc + j] = a1 + bj;
    out[2*Dc + j] = a2 + bj;
    out[3*Dc + j] = a3 + bj;
}

// ---------------------------------------------------------------------------
extern "C" void kernel_launch(void* const* d_in, const int* in_sizes, int n_in,
                              void* d_out, int out_size)
{
    const float* x  = (const float*)d_in[0];
    const float* Wq = (const float*)d_in[1];
    const float* bq = (const float*)d_in[2];
    const float* Wk = (const float*)d_in[3];
    const float* bk = (const float*)d_in[4];
    const float* Wv = (const float*)d_in[5];
    const float* bv = (const float*)d_in[6];
    const float* Wo = (const float*)d_in[7];
    const float* bo = (const float*)d_in[8];

    const size_t nconv = ((size_t)NTOK * Dc + 3 * (size_t)Dc * Dc) / 4;  // 2883584
    convert_kernel<<<(unsigned)(nconv / 256), 256>>>(x, Wq, Wk, Wv);
    qkv_mma_kernel<<<dim3(NTOK / QK_BM, Hc, 3), 256>>>(bq, bk, bv);
    score_mma_kernel<<<dim3(Tc / SC_BM, Bc * Hc), 256>>>();
    colsum_kernel<<<dim3(Tc / 512, Bc * Hc), 256>>>();
    ctx_kernel<<<Bc * Hc, 256>>>();
    out_kernel<<<Dc / 128, 128>>>(Wo, bo, (float*)d_out);
}

// round 9
// speedup vs baseline: 3.8810x; 1.3730x over previous
#include <cuda_runtime.h>
#include <cuda_fp16.h>
#include <cstdint>

#define Bc  4
#define Tc  2048
#define Dc  1024
#define Hc  16
#define HDc 64
#define NTOK (Bc * Tc)   // 8192

// ---------------- scratch (__device__ globals; no allocs allowed) ----------
__device__ __half g_xh[(size_t)NTOK * Dc];          // x in fp16
__device__ __half g_Wh[(size_t)3 * Dc * Dc];        // Wq,Wk,Wv in fp16
__device__ __half g_Qh[(size_t)NTOK * Dc];          // [B,H,T,HD] fp16 (pre-scaled by 0.125)
__device__ __half g_Kh[(size_t)NTOK * Dc];          // [B,H,T,HD] fp16
__device__ float  g_V [(size_t)NTOK * Dc];          // [B,H,T,HD] fp32
__device__ __half g_S [(size_t)Bc * Hc * Tc * Tc];  // raw scores fp16 (512 MB)
__device__ float  g_c [Bc * Hc * Tc];               // per-row m + log Z
__device__ float  g_wp[(size_t)16 * Bc * Hc * Tc];  // partial column sums (8 MB)
__device__ float  g_w [Bc * Hc * Tc];               // column weights (1/T folded)
__device__ float  g_ctx[Bc * Dc];                   // mean attn output

// ---------------- PTX helpers ---------------------------------------------
__device__ __forceinline__ uint32_t smem_u32(const void* p) {
    return (uint32_t)__cvta_generic_to_shared(p);
}
__device__ __forceinline__ void cp16(uint32_t dst, const void* src) {
    asm volatile("cp.async.cg.shared.global [%0], [%1], 16;\n" :: "r"(dst), "l"(src));
}
__device__ __forceinline__ void cp_commit() { asm volatile("cp.async.commit_group;\n"); }
template<int N> __device__ __forceinline__ void cp_wait() {
    asm volatile("cp.async.wait_group %0;\n" :: "n"(N));
}
__device__ __forceinline__ void ldsm4(uint32_t* r, uint32_t a) {
    asm volatile("ldmatrix.sync.aligned.m8n8.x4.shared.b16 {%0,%1,%2,%3},[%4];\n"
        : "=r"(r[0]), "=r"(r[1]), "=r"(r[2]), "=r"(r[3]) : "r"(a));
}
__device__ __forceinline__ void ldsm2(uint32_t* r, uint32_t a) {
    asm volatile("ldmatrix.sync.aligned.m8n8.x2.shared.b16 {%0,%1},[%2];\n"
        : "=r"(r[0]), "=r"(r[1]) : "r"(a));
}
__device__ __forceinline__ void mma16816(float* d, const uint32_t* a, const uint32_t* b) {
    asm volatile("mma.sync.aligned.m16n8k16.row.col.f32.f16.f16.f32 "
        "{%0,%1,%2,%3},{%4,%5,%6,%7},{%8,%9},{%0,%1,%2,%3};\n"
        : "+f"(d[0]), "+f"(d[1]), "+f"(d[2]), "+f"(d[3])
        : "r"(a[0]), "r"(a[1]), "r"(a[2]), "r"(a[3]), "r"(b[0]), "r"(b[1]));
}

// ---------------------------------------------------------------------------
// Kernel 0: fp32 -> fp16 conversion of x and the three projection weights.
// ---------------------------------------------------------------------------
__global__ __launch_bounds__(256) void convert_kernel(
    const float* __restrict__ x, const float* __restrict__ Wq,
    const float* __restrict__ Wk, const float* __restrict__ Wv)
{
    const size_t NX = (size_t)NTOK * Dc;       // 8388608
    const size_t NW = (size_t)Dc * Dc;         // 1048576
    size_t i = ((size_t)blockIdx.x * 256 + threadIdx.x) * 4;
    if (i < NX) {
        float4 v = *(const float4*)(x + i);
        *(__half2*)(g_xh + i)     = __floats2half2_rn(v.x, v.y);
        *(__half2*)(g_xh + i + 2) = __floats2half2_rn(v.z, v.w);
    } else {
        size_t j = i - NX;
        if (j >= 3 * NW) return;
        const float* src = (j < NW) ? (Wq + j) : (j < 2 * NW) ? (Wk + (j - NW)) : (Wv + (j - 2 * NW));
        float4 v = *(const float4*)src;
        __half* dst = g_Wh + j;
        *(__half2*)dst       = __floats2half2_rn(v.x, v.y);
        *(__half2*)(dst + 2) = __floats2half2_rn(v.z, v.w);
    }
}

// ---------------------------------------------------------------------------
// Kernel 1: QKV projection via fp16 mma (unchanged from round 4).
// ---------------------------------------------------------------------------
#define QK_BM 128
#define QK_BN 64
#define QK_BK 32
#define QK_ST 40   // 32 + 8 pad halves

__global__ __launch_bounds__(256) void qkv_mma_kernel(
    const float* __restrict__ bq, const float* __restrict__ bk,
    const float* __restrict__ bv)
{
    __shared__ __half As[2][QK_BM][QK_ST];
    __shared__ __half Bs[2][QK_BN][QK_ST];

    const int tid  = threadIdx.x;
    const int lane = tid & 31, warp = tid >> 5;
    const int wm = warp >> 2, wn = warp & 3;
    const int sel = blockIdx.z;
    const int h   = blockIdx.y;
    const int n0  = blockIdx.x * QK_BM;
    const int j0  = h * 64;
    const __half* WB   = g_Wh + (size_t)sel * Dc * Dc;
    const float*  bias = (sel == 0) ? bq : (sel == 1) ? bk : bv;

    const int arow = tid >> 1, ac0 = (tid & 1) * 2;
    const int brow = tid >> 2, bc  = tid & 3;

    float acc[4][2][4];
#pragma unroll
    for (int mt = 0; mt < 4; mt++)
#pragma unroll
        for (int nt = 0; nt < 2; nt++)
#pragma unroll
            for (int i = 0; i < 4; i++) acc[mt][nt][i] = 0.f;

    {
        const __half* sa = g_xh + (size_t)(n0 + arow) * Dc + ac0 * 8;
        uint32_t da = smem_u32(&As[0][arow][ac0 * 8]);
        cp16(da, sa); cp16(da + 16, sa + 8);
        cp16(smem_u32(&Bs[0][brow][bc * 8]), WB + (size_t)(j0 + brow) * Dc + bc * 8);
        cp_commit();
    }

    const int NKT = Dc / QK_BK;
    for (int kt = 0; kt < NKT; kt++) {
        if (kt + 1 < NKT) {
            int s = (kt + 1) & 1, k0 = (kt + 1) * QK_BK;
            const __half* sa = g_xh + (size_t)(n0 + arow) * Dc + k0 + ac0 * 8;
            uint32_t da = smem_u32(&As[s][arow][ac0 * 8]);
            cp16(da, sa); cp16(da + 16, sa + 8);
            cp16(smem_u32(&Bs[s][brow][bc * 8]), WB + (size_t)(j0 + brow) * Dc + k0 + bc * 8);
            cp_commit();
            cp_wait<1>();
        } else {
            cp_wait<0>();
        }
        __syncthreads();
        const int s = kt & 1;
#pragma unroll
        for (int ks = 0; ks < 2; ks++) {
            uint32_t af[4][4], bf[2][2];
#pragma unroll
            for (int mt = 0; mt < 4; mt++)
                ldsm4(af[mt], smem_u32(&As[s][wm * 64 + mt * 16 + (lane & 15)][ks * 16 + (lane >> 4) * 8]));
#pragma unroll
            for (int nt = 0; nt < 2; nt++)
                ldsm2(bf[nt], smem_u32(&Bs[s][wn * 16 + nt * 8 + (lane & 7)][ks * 16 + ((lane >> 3) & 1) * 8]));
#pragma unroll
            for (int mt = 0; mt < 4; mt++)
#pragma unroll
                for (int nt = 0; nt < 2; nt++)
                    mma16816(acc[mt][nt], af[mt], bf[nt]);
        }
        __syncthreads();
    }

    const int gr = lane >> 2, gc = lane & 3;
    const int b  = n0 >> 11;
#pragma unroll
    for (int mt = 0; mt < 4; mt++) {
#pragma unroll
        for (int nt = 0; nt < 2; nt++) {
            const int cw = wn * 16 + nt * 8 + gc * 2;
            const float b0 = bias[j0 + cw], b1 = bias[j0 + cw + 1];
#pragma unroll
            for (int hf = 0; hf < 2; hf++) {
                const int r = wm * 64 + mt * 16 + gr + hf * 8;
                const int t = (n0 + r) & (Tc - 1);
                const size_t off = ((size_t)((b * Hc + h) * Tc + t)) * HDc + cw;
                float v0 = acc[mt][nt][hf * 2 + 0] + b0;
                float v1 = acc[mt][nt][hf * 2 + 1] + b1;
                if (sel == 0)      *(__half2*)(g_Qh + off) = __floats2half2_rn(v0 * 0.125f, v1 * 0.125f);
                else if (sel == 1) *(__half2*)(g_Kh + off) = __floats2half2_rn(v0, v1);
                else               *(float2*)(g_V + off)   = make_float2(v0, v1);
            }
        }
    }
}

// ---------------------------------------------------------------------------
// Kernel 2: scores via fp16 mma, fused online logsumexp.  S tiles are staged
// through smem (reusing the dead Qs buffer) and flushed with 128B coalesced
// stores for full write-sector efficiency.
// ---------------------------------------------------------------------------
#define SC_BM 128
#define SC_BN 64
#define SC_ST (HDc + 8)   // 72 halves (144B stride: 16B-aligned rows)

__global__ __launch_bounds__(256) void score_mma_kernel()
{
    __shared__ __half Qs[SC_BM][SC_ST];          // Q tile, then reused as S stage
    __shared__ __half Ks[2][SC_BN][SC_ST];
    __shared__ float  redm[SC_BM][2], redz[SC_BM][2];
    __half (*St)[SC_ST] = Qs;                    // alias: Qs dead after frag preload

    const int tid = threadIdx.x, lane = tid & 31, warp = tid >> 5;
    const int wm = warp >> 1, wn = warp & 1;
    const int bh = blockIdx.y, q0 = blockIdx.x * SC_BM;
    const __half* Qg = g_Qh + ((size_t)bh * Tc + q0) * HDc;
    const __half* Kg = g_Kh + (size_t)bh * Tc * HDc;
    __half*       Sb = g_S  + (size_t)bh * Tc * Tc;

    {
        int id = tid;
#pragma unroll
        for (int it = 0; it < 4; it++, id += 256) {
            int r = id >> 3, c = id & 7;
            cp16(smem_u32(&Qs[r][c * 8]), Qg + (size_t)r * HDc + c * 8);
        }
        cp_commit();
    }
    {
        int id = tid;
#pragma unroll
        for (int it = 0; it < 2; it++, id += 256) {
            int r = id >> 3, c = id & 7;
            cp16(smem_u32(&Ks[0][r][c * 8]), Kg + (size_t)r * HDc + c * 8);
        }
        cp_commit();
    }
    cp_wait<1>();           // Q ready
    __syncthreads();

    uint32_t qf[2][4][4];
#pragma unroll
    for (int mt = 0; mt < 2; mt++)
#pragma unroll
        for (int ks = 0; ks < 4; ks++)
            ldsm4(qf[mt][ks], smem_u32(&Qs[wm * 32 + mt * 16 + (lane & 15)][ks * 16 + (lane >> 4) * 8]));

    float m_run[4], z_run[4];
#pragma unroll
    for (int i = 0; i < 4; i++) { m_run[i] = -1e30f; z_run[i] = 0.f; }

    const int gr = lane >> 2, gc = lane & 3;
    const int NKT = Tc / SC_BN;   // 32

    for (int kt = 0; kt < NKT; kt++) {
        cp_wait<0>();
        __syncthreads();   // Ks[s] ready; St flush of prev iter also complete
        const int s = kt & 1;

        float acc[2][4][4];
#pragma unroll
        for (int mt = 0; mt < 2; mt++)
#pragma unroll
            for (int nt = 0; nt < 4; nt++)
#pragma unroll
                for (int i = 0; i < 4; i++) acc[mt][nt][i] = 0.f;

#pragma unroll
        for (int ks = 0; ks < 4; ks++) {
            uint32_t bf[4][2];
#pragma unroll
            for (int nt = 0; nt < 4; nt++)
                ldsm2(bf[nt], smem_u32(&Ks[s][wn * 32 + nt * 8 + (lane & 7)][ks * 16 + ((lane >> 3) & 1) * 8]));
#pragma unroll
            for (int mt = 0; mt < 2; mt++)
#pragma unroll
                for (int nt = 0; nt < 4; nt++)
                    mma16816(acc[mt][nt], qf[mt][ks], bf[nt]);
        }
        __syncthreads();   // done reading Ks[s]

        // prefetch next K tile (overlaps with epilogue below)
        if (kt + 1 < NKT) {
            int id = tid, k0 = (kt + 1) * SC_BN, sn = (kt + 1) & 1;
#pragma unroll
            for (int it = 0; it < 2; it++, id += 256) {
                int r = id >> 3, c = id & 7;
                cp16(smem_u32(&Ks[sn][r][c * 8]), Kg + (size_t)(k0 + r) * HDc + c * 8);
            }
            cp_commit();
        }

        // epilogue: online (m,z) update + stage tile to smem
#pragma unroll
        for (int mt = 0; mt < 2; mt++) {
#pragma unroll
            for (int hf = 0; hf < 2; hf++) {
                const int li = mt * 2 + hf;
                float v[8];
#pragma unroll
                for (int nt = 0; nt < 4; nt++) {
                    v[nt * 2]     = acc[mt][nt][hf * 2 + 0];
                    v[nt * 2 + 1] = acc[mt][nt][hf * 2 + 1];
                }
                float mx = v[0];
#pragma unroll
                for (int i = 1; i < 8; i++) mx = fmaxf(mx, v[i]);
                float nm = fmaxf(m_run[li], mx);
                float za = 0.f;
#pragma unroll
                for (int i = 0; i < 8; i++) za += __expf(v[i] - nm);
                z_run[li] = z_run[li] * __expf(m_run[li] - nm) + za;
                m_run[li] = nm;

                const int r = wm * 32 + mt * 16 + gr + hf * 8;
#pragma unroll
                for (int nt = 0; nt < 4; nt++)
                    *(__half2*)&St[r][wn * 32 + nt * 8 + gc * 2] =
                        __floats2half2_rn(v[nt * 2], v[nt * 2 + 1]);
            }
        }
        __syncthreads();   // stage complete

        // flush tile: 128B-coalesced stores
        {
            int id = tid;
#pragma unroll
            for (int it = 0; it < 4; it++, id += 256) {
                int r = id >> 3, c = (id & 7) * 8;
                *(uint4*)(Sb + (size_t)(q0 + r) * Tc + kt * SC_BN + c) =
                    *(const uint4*)&St[r][c];
            }
        }
        // loop-head __syncthreads protects St from next-iter overwrite
    }

    // reduce (m,z): quad via shfl, then the 2 n-warps via smem
#pragma unroll
    for (int li = 0; li < 4; li++) {
#pragma unroll
        for (int d = 1; d < 4; d <<= 1) {
            float om = __shfl_xor_sync(0xffffffffu, m_run[li], d);
            float oz = __shfl_xor_sync(0xffffffffu, z_run[li], d);
            float nm = fmaxf(m_run[li], om);
            z_run[li] = z_run[li] * __expf(m_run[li] - nm) + oz * __expf(om - nm);
            m_run[li] = nm;
        }
    }
    __syncthreads();
    if (gc == 0) {
#pragma unroll
        for (int li = 0; li < 4; li++) {
            const int r = wm * 32 + (li >> 1) * 16 + gr + (li & 1) * 8;
            redm[r][wn] = m_run[li];
            redz[r][wn] = z_run[li];
        }
    }
    __syncthreads();
    if (tid < SC_BM) {
        float m0 = redm[tid][0], m1 = redm[tid][1];
        float z0 = redz[tid][0], z1 = redz[tid][1];
        float nm = fmaxf(m0, m1);
        float Z  = z0 * __expf(m0 - nm) + z1 * __expf(m1 - nm);
        g_c[bh * Tc + q0 + tid] = nm + __logf(Z);
    }
}

// ---------------------------------------------------------------------------
// Kernel 3a: partial column sums over 128-query chunks.
// grid (16 chunks, 64 bh), 256 threads, each thread owns 8 columns (uint4).
// ---------------------------------------------------------------------------
__global__ __launch_bounds__(256) void colsum_part_kernel()
{
    const int bh = blockIdx.y;
    const int ch = blockIdx.x;
    const int k0 = threadIdx.x * 8;
    const __half* Sb = g_S + (size_t)bh * Tc * Tc;
    const float*  cb = g_c + bh * Tc;

    float a[8];
#pragma unroll
    for (int i = 0; i < 8; i++) a[i] = 0.f;

    const int q0 = ch * 128;
#pragma unroll 2
    for (int q = q0; q < q0 + 128; q++) {
        uint4 raw = *(const uint4*)(Sb + (size_t)q * Tc + k0);
        float c = cb[q];
        const __half2* h = (const __half2*)&raw;
#pragma unroll
        for (int j = 0; j < 4; j++) {
            float2 v = __half22float2(h[j]);
            a[2 * j]     += __expf(v.x - c);
            a[2 * j + 1] += __expf(v.y - c);
        }
    }
    float* dst = g_wp + ((size_t)(bh * 16 + ch)) * Tc + k0;
    *(float4*)dst       = make_float4(a[0], a[1], a[2], a[3]);
    *(float4*)(dst + 4) = make_float4(a[4], a[5], a[6], a[7]);
}

// ---------------------------------------------------------------------------
// Kernel 3b: fold 16 partials -> w[k]  (131072 outputs)
// ---------------------------------------------------------------------------
__global__ __launch_bounds__(256) void wreduce_kernel()
{
    const int idx = blockIdx.x * 256 + threadIdx.x;   // bh*2048 + k
    const int bh = idx >> 11, k = idx & (Tc - 1);
    float s = 0.f;
#pragma unroll
    for (int ch = 0; ch < 16; ch++)
        s += g_wp[((size_t)(bh * 16 + ch)) * Tc + k];
    g_w[idx] = s * (1.0f / Tc);
}

// ---------------------------------------------------------------------------
// Kernel 4: ctx[b, h*64+d] = sum_k w[b,h,k] * V[b,h,k,d]
// ---------------------------------------------------------------------------
__global__ __launch_bounds__(256) void ctx_kernel()
{
    const int bh   = blockIdx.x;
    const int d    = threadIdx.x & 63;
    const int part = threadIdx.x >> 6;
    const float* Vb = g_V + (size_t)bh * Tc * HDc;
    const float* wb = g_w + bh * Tc;
    float acc = 0.f;
    const int kb = part * (Tc / 4);
    for (int k = kb; k < kb + Tc / 4; k++)
        acc += wb[k] * Vb[(size_t)k * HDc + d];
    __shared__ float red[4][64];
    red[part][d] = acc;
    __syncthreads();
    if (part == 0) {
        int b = bh >> 4, h = bh & 15;
        g_ctx[b * Dc + h * HDc + d] = red[0][d] + red[1][d] + red[2][d] + red[3][d];
    }
}

// ---------------------------------------------------------------------------
// Kernel 5: out[b, j] = sum_i ctx[b,i] * Wo[j,i] + bo[j]
// ---------------------------------------------------------------------------
__global__ __launch_bounds__(128) void out_kernel(
    const float* __restrict__ Wo, const float* __restrict__ bo,
    float* __restrict__ out)
{
    __shared__ float cs[Bc * Dc];
    const int tid = threadIdx.x;
    for (int i = tid; i < Bc * Dc; i += 128) cs[i] = g_ctx[i];
    __syncthreads();
    const int j = blockIdx.x * 128 + tid;
    const float* wr = Wo + (size_t)j * Dc;
    float a0 = 0.f, a1 = 0.f, a2 = 0.f, a3 = 0.f;
    for (int i = 0; i < Dc; i += 4) {
        float4 wv = *(const float4*)(wr + i);
        a0 += cs[i]*wv.x      + cs[i+1]*wv.y      + cs[i+2]*wv.z      + cs[i+3]*wv.w;
        a1 += cs[Dc+i]*wv.x   + cs[Dc+i+1]*wv.y   + cs[Dc+i+2]*wv.z   + cs[Dc+i+3]*wv.w;
        a2 += cs[2*Dc+i]*wv.x + cs[2*Dc+i+1]*wv.y + cs[2*Dc+i+2]*wv.z + cs[2*Dc+i+3]*wv.w;
        a3 += cs[3*Dc+i]*wv.x + cs[3*Dc+i+1]*wv.y + cs[3*Dc+i+2]*wv.z + cs[3*Dc+i+3]*wv.w;
    }
    float bj = bo[j];
    out[0*Dc + j] = a0 + bj;
    out[1*Dc + j] = a1 + bj;
    out[2*Dc + j] = a2 + bj;
    out[3*Dc + j] = a3 + bj;
}

// ---------------------------------------------------------------------------
extern "C" void kernel_launch(void* const* d_in, const int* in_sizes, int n_in,
                              void* d_out, int out_size)
{
    const float* x  = (const float*)d_in[0];
    const float* Wq = (const float*)d_in[1];
    const float* bq = (const float*)d_in[2];
    const float* Wk = (const float*)d_in[3];
    const float* bk = (const float*)d_in[4];
    const float* Wv = (const float*)d_in[5];
    const float* bv = (const float*)d_in[6];
    const float* Wo = (const float*)d_in[7];
    const float* bo = (const float*)d_in[8];

    const size_t nconv = ((size_t)NTOK * Dc + 3 * (size_t)Dc * Dc) / 4;  // 2883584
    convert_kernel<<<(unsigned)(nconv / 256), 256>>>(x, Wq, Wk, Wv);
    qkv_mma_kernel<<<dim3(NTOK / QK_BM, Hc, 3), 256>>>(bq, bk, bv);
    score_mma_kernel<<<dim3(Tc / SC_BM, Bc * Hc), 256>>>();
    colsum_part_kernel<<<dim3(16, Bc * Hc), 256>>>();
    wreduce_kernel<<<(Bc * Hc * Tc) / 256, 256>>>();
    ctx_kernel<<<Bc * Hc, 256>>>();
    out_kernel<<<Dc / 128, 128>>>(Wo, bo, (float*)d_out);
}